// round 7
// baseline (speedup 1.0000x reference)
#include <cuda_runtime.h>
#include <cstdint>

#define DIMC 64
#define NBINS 4096
#define CHUNKS 6            // 64 rows per hist block (two 32-row passes)
#define IMG 384
#define WORDS 12            // 384 / 32
#define BATCH 32
#define OUTW 65
#define HIST_BLOCKS (BATCH * CHUNKS)    // 192
#define LUT_BLOCKS 64
#define RB_BINS 128         // reduce: bins per block
#define RD_IMGS 8           // reduce: images per block
#define BIN_GROUPS (NBINS / RB_BINS)    // 32
#define IMG_GROUPS (BATCH / RD_IMGS)    // 4
#define KCH (RB_BINS / 4)   // 32 lut registers per thread

// Static device scratch (no allocations allowed)
__device__ float g_lut[NBINS * DIMC];               // 1 MB
__device__ int   g_part[HIST_BLOCKS * NBINS];       // 3 MB per-block partials

// ---------------------------------------------------------------------------
// Fused kernel: blocks [0,192) histogram 64-row chunks (two software-
// pipelined 32-row passes) and flush via int4 STG; blocks [192,256) build
// the 12-bit pair LUT and zero d_out. One launch, one wave.
// ---------------------------------------------------------------------------
__global__ __launch_bounds__(384) void fused_kernel(
    const float* __restrict__ alpha,
    const float* __restrict__ w, const float* __restrict__ bias,
    const float* __restrict__ gamma, const float* __restrict__ beta,
    const float* __restrict__ mean, const float* __restrict__ var,
    float* __restrict__ out)
{
    int tid = threadIdx.x;

    if (blockIdx.x >= HIST_BLOCKS) {
        // ---------------- LUT role ----------------
        int t = (blockIdx.x - HIST_BLOCKS) * 384 + tid;   // 0 .. 24575
        if (t < BATCH * OUTW) out[t] = 0.0f;              // zero-init output

        int c  = t & (DIMC - 1);
        int p0 = t >> 6;                                  // 0..383

        float A = gamma[c] * rsqrtf(var[c] + 1e-5f);
        float base = (bias[c] - mean[c]) * A + beta[c];
        float wk[9];
#pragma unroll
        for (int k = 0; k < 9; ++k) wk[k] = w[c * 9 + k];

        for (int p = p0; p < NBINS; p += 384) {
            float da = 0.f, db = 0.f;
#pragma unroll
            for (int ky = 0; ky < 3; ++ky)
#pragma unroll
                for (int kx = 0; kx < 3; ++kx) {
                    int bp = 4 * ky + kx;
                    if ((p >> bp) & 1)       da += wk[ky * 3 + kx];
                    if ((p >> (bp + 1)) & 1) db += wk[ky * 3 + kx];
                }
            float va = fmaxf(fmaf(A, da, base), 0.f);
            float vb = fmaxf(fmaf(A, db, base), 0.f);
            g_lut[p * DIMC + c] = (va + vb) * (1.0f / (384.0f * 384.0f));
        }
        return;
    }

    // ---------------- histogram role ----------------
    __shared__ uint32_t bits[2][34][WORDS + 2];   // double-buffered bit planes
    __shared__ int hist[NBINS];

    int b     = blockIdx.x / CHUNKS;
    int chunk = blockIdx.x % CHUNKS;
    int lane  = tid & 31;
    int warp  = tid >> 5;                      // 0..11 = word column

    for (int i = tid; i < NBINS; i += 384) hist[i] = 0;
    if (tid < 34) {
        bits[0][tid][0] = 0u; bits[0][tid][WORDS + 1] = 0u;
        bits[1][tid][0] = 0u; bits[1][tid][WORDS + 1] = 0u;
    }

    const float* img = alpha + (size_t)b * IMG * IMG;
    int r  = tid / WORDS;   // 0..31 local row  (384 = 32*12 exactly)
    int wd = tid % WORDS;
    int base0 = chunk * 64;
    int base1 = chunk * 64 + 32;

    // ---- pass 0: batched loads, ballots ----
    float v[34];
#pragma unroll
    for (int row = 0; row < 34; ++row) {
        int g = base0 - 1 + row;
        v[row] = (g >= 0 && g < IMG) ? img[g * IMG + warp * 32 + lane] : 0.0f;
    }
#pragma unroll
    for (int row = 0; row < 34; ++row) {
        uint32_t wb = __ballot_sync(0xffffffffu, ((int)(v[row] * 255.0f)) & 1);
        if (lane == 0) bits[0][row][warp + 1] = wb;
    }
    __syncthreads();

    uint32_t p0 = bits[0][r][wd],     c0 = bits[0][r][wd + 1],     x0 = bits[0][r][wd + 2];
    uint32_t p1 = bits[0][r + 1][wd], c1 = bits[0][r + 1][wd + 1], x1 = bits[0][r + 1][wd + 2];
    uint32_t p2 = bits[0][r + 2][wd], c2 = bits[0][r + 2][wd + 1], x2 = bits[0][r + 2][wd + 2];

    // ---- issue pass-1 loads NOW (hide DRAM behind pass-0 atomics) ----
    float u[34];
#pragma unroll
    for (int row = 0; row < 34; ++row) {
        int g = base1 - 1 + row;
        u[row] = (g < IMG) ? img[g * IMG + warp * 32 + lane] : 0.0f;  // base1-1 >= 31 always
    }

    // ---- pass-0 shared atomics ----
    {
        uint32_t n0 = __funnelshift_r(p0, c0, 31) & 0xF;
        uint32_t n1 = __funnelshift_r(p1, c1, 31) & 0xF;
        uint32_t n2 = __funnelshift_r(p2, c2, 31) & 0xF;
        atomicAdd(&hist[n0 | (n1 << 4) | (n2 << 8)], 1);
    }
#pragma unroll
    for (int k = 1; k < 16; ++k) {
        uint32_t n0 = __funnelshift_r(c0, x0, 2 * k - 1) & 0xF;
        uint32_t n1 = __funnelshift_r(c1, x1, 2 * k - 1) & 0xF;
        uint32_t n2 = __funnelshift_r(c2, x2, 2 * k - 1) & 0xF;
        atomicAdd(&hist[n0 | (n1 << 4) | (n2 << 8)], 1);
    }

    // ---- pass-1 ballots into second buffer ----
#pragma unroll
    for (int row = 0; row < 34; ++row) {
        uint32_t wb = __ballot_sync(0xffffffffu, ((int)(u[row] * 255.0f)) & 1);
        if (lane == 0) bits[1][row][warp + 1] = wb;
    }
    __syncthreads();

    p0 = bits[1][r][wd];     c0 = bits[1][r][wd + 1];     x0 = bits[1][r][wd + 2];
    p1 = bits[1][r + 1][wd]; c1 = bits[1][r + 1][wd + 1]; x1 = bits[1][r + 1][wd + 2];
    p2 = bits[1][r + 2][wd]; c2 = bits[1][r + 2][wd + 1]; x2 = bits[1][r + 2][wd + 2];

    {
        uint32_t n0 = __funnelshift_r(p0, c0, 31) & 0xF;
        uint32_t n1 = __funnelshift_r(p1, c1, 31) & 0xF;
        uint32_t n2 = __funnelshift_r(p2, c2, 31) & 0xF;
        atomicAdd(&hist[n0 | (n1 << 4) | (n2 << 8)], 1);
    }
#pragma unroll
    for (int k = 1; k < 16; ++k) {
        uint32_t n0 = __funnelshift_r(c0, x0, 2 * k - 1) & 0xF;
        uint32_t n1 = __funnelshift_r(c1, x1, 2 * k - 1) & 0xF;
        uint32_t n2 = __funnelshift_r(c2, x2, 2 * k - 1) & 0xF;
        atomicAdd(&hist[n0 | (n1 << 4) | (n2 << 8)], 1);
    }
    __syncthreads();

    // cheap vectorized flush (STG.128, no atomics)
    int4* dst = (int4*)(g_part + blockIdx.x * NBINS);
    const int4* src = (const int4*)hist;
    for (int i = tid; i < NBINS / 4; i += 384) dst[i] = src[i];
}

// ---------------------------------------------------------------------------
// Reduce: grid (32 bin-groups, 4 image-octets) = 128 blocks × 256 threads.
// One register-resident LUT burst (32 coalesced loads) serves 8 image
// accumulator chains -> LUT L2 traffic 4 MB total. Merge: 6 batched int4
// loads per thread covering 8 images × 128 bins.
// ---------------------------------------------------------------------------
__global__ __launch_bounds__(256) void reduce_kernel(
    const float* __restrict__ alpha, float* __restrict__ out)
{
    __shared__ float cnt[RD_IMGS][RB_BINS];   // 4 KB
    __shared__ float red[4][RD_IMGS][DIMC];   // 8 KB

    int tid = threadIdx.x;
    int cg  = blockIdx.x;                     // bins [cg*128, cg*128+128)
    int ig  = blockIdx.y;                     // images [ig*8, ig*8+8)

    int c = tid & 63;
    int g = tid >> 6;                         // 0..3 bin sub-chain

    // LUT into registers: one fully-batched, coalesced burst (MLP=32)
    const float* lut = g_lut + (size_t)cg * RB_BINS * DIMC + c;
    float l[KCH];
#pragma unroll
    for (int k = 0; k < KCH; ++k) l[k] = lut[(4 * k + g) * DIMC];

    // Phase 1: merge 6 partials; thread = (image i, bin quad q)
    {
        int i = tid >> 5;                     // 0..7 image within octet
        int q = tid & 31;                     // int4 quad (bins 4q..4q+3)
        int b = ig * RD_IMGS + i;
        const int4* part =
            (const int4*)(g_part + (b * CHUNKS) * NBINS + cg * RB_BINS) + q;
        int4 s = make_int4(0, 0, 0, 0);
#pragma unroll
        for (int j = 0; j < CHUNKS; ++j) {
            int4 p = part[j * (NBINS / 4)];
            s.x += p.x; s.y += p.y; s.z += p.z; s.w += p.w;
        }
        cnt[i][4 * q + 0] = (float)s.x;
        cnt[i][4 * q + 1] = (float)s.y;
        cnt[i][4 * q + 2] = (float)s.z;
        cnt[i][4 * q + 3] = (float)s.w;
    }
    __syncthreads();

    // Phase 2: 32 iterations × {8 broadcast LDS + 8 independent FMA chains}
    float a0 = 0.f, a1 = 0.f, a2 = 0.f, a3 = 0.f;
    float a4 = 0.f, a5 = 0.f, a6 = 0.f, a7 = 0.f;
#pragma unroll
    for (int k = 0; k < KCH; ++k) {
        int bin = 4 * k + g;
        float lk = l[k];
        a0 = fmaf(cnt[0][bin], lk, a0);
        a1 = fmaf(cnt[1][bin], lk, a1);
        a2 = fmaf(cnt[2][bin], lk, a2);
        a3 = fmaf(cnt[3][bin], lk, a3);
        a4 = fmaf(cnt[4][bin], lk, a4);
        a5 = fmaf(cnt[5][bin], lk, a5);
        a6 = fmaf(cnt[6][bin], lk, a6);
        a7 = fmaf(cnt[7][bin], lk, a7);
    }
    red[g][0][c] = a0; red[g][1][c] = a1; red[g][2][c] = a2; red[g][3][c] = a3;
    red[g][4][c] = a4; red[g][5][c] = a5; red[g][6][c] = a6; red[g][7][c] = a7;
    __syncthreads();

    // combine sub-chains, accumulate into out (512 outputs, 2 per thread)
#pragma unroll
    for (int t = tid; t < RD_IMGS * DIMC; t += 256) {
        int i  = t >> 6;
        int ch = t & 63;
        float s = red[0][i][ch] + red[1][i][ch] + red[2][i][ch] + red[3][i][ch];
        atomicAdd(&out[(ig * RD_IMGS + i) * OUTW + ch], s);
    }

    // marker check: one thread total; broadcast to all 32 rows
    if (cg == 0 && ig == 0 && tid == 0) {
        uint32_t word = 0u;
#pragma unroll
        for (int j = 0; j < 32; ++j) {
            int bit = ((int)(alpha[j] * 255.0f)) & 1;
            word |= (uint32_t)bit << j;
        }
        float m = (__brev(word) == 0x41493234u) ? 1.0f : 0.0f;   // 'AI24'
        for (int bb = 0; bb < BATCH; ++bb) out[bb * OUTW + DIMC] = m;
    }
}

// ---------------------------------------------------------------------------
extern "C" void kernel_launch(void* const* d_in, const int* in_sizes, int n_in,
                              void* d_out, int out_size)
{
    const float* alpha  = (const float*)d_in[0];
    const float* conv_w = (const float*)d_in[1];
    const float* conv_b = (const float*)d_in[2];
    const float* bn_g   = (const float*)d_in[3];
    const float* bn_b   = (const float*)d_in[4];
    const float* bn_m   = (const float*)d_in[5];
    const float* bn_v   = (const float*)d_in[6];
    float* out = (float*)d_out;

    fused_kernel<<<HIST_BLOCKS + LUT_BLOCKS, 384>>>(
        alpha, conv_w, conv_b, bn_g, bn_b, bn_m, bn_v, out);
    reduce_kernel<<<dim3(BIN_GROUPS, IMG_GROUPS), 256>>>(alpha, out);
}